// round 16
// baseline (speedup 1.0000x reference)
#include <cuda_runtime.h>
#include <math.h>
#include <stdint.h>

#define NUM_SCALES 16
#define MAXP 524288u
#define HMASK (MAXP - 1u)
#define TPB 128
#define NBINS (1 << 20)
#define MAXQ 1048576
#define NTILE 1024   // scan tiles (each covers 1024 bins)

struct Cfg {
    float rx[NUM_SCALES], ry[NUM_SCALES], rz[NUM_SCALES], rt[NUM_SCALES];
    unsigned s1[NUM_SCALES], s2[NUM_SCALES], s3[NUM_SCALES];
    unsigned dense[NUM_SCALES];
    unsigned off2[NUM_SCALES];   // level offset in float2 units (16B-aligned: p % 8 == 0)
};

// ---- scratch (static device globals; no allocation) ----
// g_cnt: histogram counters. INVARIANT: all-zero at the start of every
// kernel_launch call (zero-initialized at load; scan_p3 re-zeros it each run).
__device__ int g_cnt[NBINS];
__device__ int g_off[NBINS];    // exclusive prefix offsets (read-only after scan_p3)
__device__ int g_bsum[NTILE];
__device__ unsigned g_key[MAXQ];   // [31:20] within-bin rank, [19:0] Morton bin
__device__ int g_perm[MAXQ];

// ---- Morton key: 5 bits per dim interleaved -> 20-bit key ----
__device__ __forceinline__ unsigned spread5(unsigned v) {
    return (v & 1u) | ((v & 2u) << 3) | ((v & 4u) << 6) | ((v & 8u) << 9) | ((v & 16u) << 12);
}
__device__ __forceinline__ unsigned morton_key(float4 p) {
    unsigned kx = (unsigned)(p.x * 32.0f);
    unsigned ky = (unsigned)(p.y * 32.0f);
    unsigned kz = (unsigned)(p.z * 32.0f);
    unsigned kt = (unsigned)(p.w * 32.0f);
    kx = kx > 31u ? 31u : kx; ky = ky > 31u ? 31u : ky;
    kz = kz > 31u ? 31u : kz; kt = kt > 31u ? 31u : kt;
    return spread5(kx) | (spread5(ky) << 1) | (spread5(kz) << 2) | (spread5(kt) << 3);
}

// histogram; the atomic's return value IS the within-bin rank -> pack into key
// (bins hold ~1 query each at 2^20 bins; rank always fits in 12 bits)
__global__ void hist_kernel(const float4* __restrict__ xyzt, int nq) {
    int i = blockIdx.x * blockDim.x + threadIdx.x;
    if (i < nq) {
        unsigned k = morton_key(xyzt[i]);
        unsigned r = (unsigned)atomicAdd(&g_cnt[k], 1);
        g_key[i] = k | (r << 20);
    }
}

// phase 1: per-tile sums (1024 tiles x 1024 bins), shuffle reduction
__global__ __launch_bounds__(256) void scan_p1() {
    __shared__ int warpsum[8];
    int t = threadIdx.x;
    int4 v = ((const int4*)g_cnt)[blockIdx.x * 256 + t];
    int s = v.x + v.y + v.z + v.w;
#pragma unroll
    for (int off = 16; off > 0; off >>= 1)
        s += __shfl_down_sync(0xFFFFFFFFu, s, off);
    if ((t & 31) == 0) warpsum[t >> 5] = s;
    __syncthreads();
    if (t < 8) {
        int w = warpsum[t];
#pragma unroll
        for (int off = 4; off > 0; off >>= 1)
            w += __shfl_down_sync(0xFFu, w, off);
        if (t == 0) g_bsum[blockIdx.x] = w;
    }
}

// phase 2+3 fused: every block redundantly scans the 1024 tile sums to get its
// own exclusive base, does its local scan into g_off, and RE-ZEROS g_cnt so the
// next graph replay's histogram starts from zero.
__global__ __launch_bounds__(256) void scan_p3() {
    __shared__ int sc[256];
    __shared__ int tilebase_sh;
    int t = threadIdx.x;

    // --- redundant scan of tile sums; extract exclusive prefix for this tile ---
    {
        int4 b4 = ((const int4*)g_bsum)[t];            // tiles 4t..4t+3
        int mysum = b4.x + b4.y + b4.z + b4.w;
        int lane = t & 31, wid = t >> 5;
        int val = mysum;
#pragma unroll
        for (int off = 1; off < 32; off <<= 1) {
            int u = __shfl_up_sync(0xFFFFFFFFu, val, off);
            if (lane >= off) val += u;
        }
        __shared__ int wtot[8];
        if (lane == 31) wtot[wid] = val;
        __syncthreads();
        int wbase = 0;
#pragma unroll
        for (int w = 0; w < 8; ++w) wbase += (w < wid) ? wtot[w] : 0;
        int thr_excl = wbase + val - mysum;            // exclusive prefix of tile 4t
        int tgt = blockIdx.x >> 2, slot = blockIdx.x & 3;
        if (t == tgt) {
            int base = thr_excl;
            if (slot > 0) base += b4.x;
            if (slot > 1) base += b4.y;
            if (slot > 2) base += b4.z;
            tilebase_sh = base;
        }
        __syncthreads();
    }
    int tilebase = tilebase_sh;

    // --- local exclusive scan over this tile's 1024 bins -> g_off; zero g_cnt ---
    int gi = blockIdx.x * 256 + t;
    int4 v = ((const int4*)g_cnt)[gi];
    int tsum = v.x + v.y + v.z + v.w;
    sc[t] = tsum;
    __syncthreads();
    for (int off = 1; off < 256; off <<= 1) {
        int u = (t >= off) ? sc[t - off] : 0;
        __syncthreads();
        sc[t] += u;
        __syncthreads();
    }
    int base = tilebase + sc[t] - tsum;
    int4 o;
    o.x = base;
    o.y = base + v.x;
    o.z = base + v.x + v.y;
    o.w = base + v.x + v.y + v.z;
    ((int4*)g_off)[gi] = o;
    ((int4*)g_cnt)[gi] = make_int4(0, 0, 0, 0);   // reset for next replay
}

// scatter: ATOMIC-FREE. pos = bin base + rank (both precomputed).
// 4 queries/thread for ILP on the load->load->store chain.
__global__ void scatter_kernel(int nq) {
    int i0 = (blockIdx.x * blockDim.x + threadIdx.x) * 4;
#pragma unroll
    for (int u = 0; u < 4; ++u) {
        int i = i0 + u;
        if (i < nq) {
            unsigned kr = g_key[i];
            int pos = g_off[kr & 0xFFFFFu] + (int)(kr >> 20);
            g_perm[pos] = i;
        }
    }
}

// ---------------- main encode ----------------

struct LvlBuf {
    float4 f4[8];     // aligned pair-words: entries {2m, 2m+1} containing corner 2j
    float2 fb[8];     // fallback load of corner 2j+1 when pair not adjacent
    float fx, fy, fz, ft;
    unsigned masks;   // bits 0-7: corner 2j in high half; bits 8-15: pair adjacent
};

__device__ __forceinline__ void level_issue(
    const Cfg& cfg, int s, float4 p, const float2* __restrict__ tbl,
    LvlBuf& B)
{
    float px = p.x * cfg.rx[s];
    float py = p.y * cfg.ry[s];
    float pz = p.z * cfg.rz[s];
    float pt = p.w * cfg.rt[s];
    float gx = floorf(px), gy = floorf(py), gz = floorf(pz), gt = floorf(pt);
    B.fx = px - gx; B.fy = py - gy; B.fz = pz - gz; B.ft = pt - gt;
    unsigned ix = (unsigned)(int)gx, iy = (unsigned)(int)gy;
    unsigned iz = (unsigned)(int)gz, it = (unsigned)(int)gt;

    const float2* __restrict__ base = tbl + cfg.off2[s];
    const float4* __restrict__ base4 = (const float4*)base;

    unsigned a[8], b[8];
    if (cfg.dense[s]) {
        unsigned t1 = cfg.s1[s], t2 = cfg.s2[s], t3 = cfg.s3[s];
        unsigned b0 = ix + iy * t1 + iz * t2 + it * t3;
#pragma unroll
        for (int j = 0; j < 8; ++j) {
            unsigned byzt = b0 + ((j & 1) ? t1 : 0u) + ((j & 2) ? t2 : 0u) + ((j & 4) ? t3 : 0u);
            a[j] = byzt;
            b[j] = byzt + 1u;
        }
    } else {
        unsigned hy0 = iy * 2654435761u, hy1 = (iy + 1u) * 2654435761u;
        unsigned hz0 = iz * 805459861u,  hz1 = (iz + 1u) * 805459861u;
        unsigned ht0 = it * 3674653429u, ht1 = (it + 1u) * 3674653429u;
#pragma unroll
        for (int j = 0; j < 8; ++j) {
            unsigned r = ((j & 1) ? hy1 : hy0) ^ ((j & 2) ? hz1 : hz0) ^ ((j & 4) ? ht1 : ht0);
            a[j] = (ix ^ r) & HMASK;
            b[j] = ((ix + 1u) ^ r) & HMASK;
        }
    }

    unsigned masks = 0u;
#pragma unroll
    for (int j = 0; j < 8; ++j) {
        B.f4[j] = __ldg(base4 + (a[j] >> 1));
        masks |= (a[j] & 1u) << j;
        masks |= ((a[j] ^ b[j]) == 1u ? 256u : 0u) << j;
    }
#pragma unroll
    for (int j = 0; j < 8; ++j) {
        if ((a[j] ^ b[j]) != 1u)
            B.fb[j] = __ldg(base + b[j]);
    }
    B.masks = masks;
}

__device__ __forceinline__ float2 level_consume(const LvlBuf& B)
{
    float fx = B.fx, fy = B.fy, fz = B.fz, ft = B.ft;
    float wx0 = 1.f - fx, wy0 = 1.f - fy, wz0 = 1.f - fz, wt0 = 1.f - ft;
    float wxy[4] = {wx0 * wy0, fx * wy0, wx0 * fy, fx * fy};
    float wzt[4] = {wz0 * wt0, fz * wt0, wz0 * ft, fz * ft};

    float o0 = 0.f, o1 = 0.f;
#pragma unroll
    for (int j = 0; j < 8; ++j) {
        bool hi  = (B.masks >> j) & 1u;
        bool adj = (B.masks >> (j + 8)) & 1u;
        float4 q = B.f4[j];
        float c0x = hi ? q.z : q.x, c0y = hi ? q.w : q.y;
        float c1x = hi ? q.x : q.z, c1y = hi ? q.y : q.w;
        if (!adj) { c1x = B.fb[j].x; c1y = B.fb[j].y; }
        float wz = wzt[j >> 1];
        float w0 = wxy[(j & 1) * 2]     * wz;
        float w1 = wxy[(j & 1) * 2 + 1] * wz;
        o0 = fmaf(w0, c0x, o0); o1 = fmaf(w0, c0y, o1);
        o0 = fmaf(w1, c1x, o0); o1 = fmaf(w1, c1y, o1);
    }
    return make_float2(o0, o1);
}

__global__ __launch_bounds__(TPB, 3) void henc_kernel(
    const float4* __restrict__ xyzt,
    const float2* __restrict__ tbl,
    float2* __restrict__ out2,
    Cfg cfg, int nq)
{
    __shared__ float2 sm2[TPB * 17];
    __shared__ int qsh[TPB];
    const int tid = threadIdx.x;
    const int i = blockIdx.x * TPB + tid;

    int q = (i < nq) ? g_perm[i] : -1;
    qsh[tid] = q;
    float4 p = (q >= 0) ? __ldg(&xyzt[q]) : make_float4(0.f, 0.f, 0.f, 0.f);

    LvlBuf A, B;
    level_issue(cfg, 0, p, tbl, A);

#pragma unroll 1
    for (int s = 0; s < NUM_SCALES; s += 2) {
        level_issue(cfg, s + 1, p, tbl, B);
        sm2[tid * 17 + s] = level_consume(A);
        if (s + 2 < NUM_SCALES)
            level_issue(cfg, s + 2, p, tbl, A);
        sm2[tid * 17 + s + 1] = level_consume(B);
    }

    __syncthreads();

    // scattered row store: 2 rows per warp-instruction (2 lines/wavefront)
#pragma unroll
    for (int k = 0; k < 16; ++k) {
        int m = tid + k * TPB;
        int row = m >> 4, chunk = m & 15;
        int qr = qsh[row];
        if (qr >= 0) out2[qr * 16 + chunk] = sm2[row * 17 + chunk];
    }
}

extern "C" void kernel_launch(void* const* d_in, const int* in_sizes, int n_in,
                              void* d_out, int out_size)
{
    (void)n_in; (void)out_size;

    // Rebuild the reference's build_config() with the same float64 libm math.
    Cfg cfg;
    const double minr[4] = {16.0, 16.0, 16.0, 16.0};
    const double maxr[4] = {256.0, 256.0, 256.0, 128.0};
    double b[4];
    for (int d = 0; d < 4; ++d)
        b[d] = exp((log(maxr[d]) - log(minr[d])) / (double)(NUM_SCALES - 1));

    unsigned long long totalp = 0;
    for (int s = 0; s < NUM_SCALES; ++s) {
        long long res[4];
        for (int d = 0; d < 4; ++d)
            res[d] = (long long)ceil(minr[d] * pow(b[d], (double)s));
        long long raw = (res[0] + 1) * (res[1] + 1) * (res[2] + 1) * (res[3] + 1);
        long long pp = (raw % 8 == 0) ? raw : ((raw + 7) / 8) * 8;
        if (pp > (long long)MAXP) pp = (long long)MAXP;

        cfg.dense[s] = (raw <= pp) ? 1u : 0u;
        cfg.rx[s] = (float)res[0];
        cfg.ry[s] = (float)res[1];
        cfg.rz[s] = (float)res[2];
        cfg.rt[s] = (float)res[3];
        cfg.s1[s] = (unsigned)(res[0] + 1);
        cfg.s2[s] = (unsigned)((res[0] + 1) * (res[1] + 1));
        cfg.s3[s] = (unsigned)((res[0] + 1) * (res[1] + 1) * (res[2] + 1));
        cfg.off2[s] = (unsigned)totalp;
        totalp += (unsigned long long)pp;
    }

    int nq = in_sizes[0] / 4;
    const float4* xyzt = (const float4*)d_in[0];
    const float2* tbl  = (const float2*)d_in[1];
    float2* out2 = (float2*)d_out;

    // 1) Morton binning (counting sort, 2^20 bins). g_cnt is all-zero here:
    //    zero-init at module load, re-zeroed by scan_p3 on every run.
    hist_kernel<<<(nq + 255) / 256, 256>>>(xyzt, nq);
    scan_p1<<<NTILE, 256>>>();
    scan_p3<<<NTILE, 256>>>();   // tile-base scan + local scan -> g_off; zeros g_cnt
    scatter_kernel<<<(nq + 1023) / 1024, 256>>>(nq);

    // 2) encode in sorted order
    int blocks = (nq + TPB - 1) / TPB;
    henc_kernel<<<blocks, TPB>>>(xyzt, tbl, out2, cfg, nq);
}

// round 17
// speedup vs baseline: 1.0059x; 1.0059x over previous
#include <cuda_runtime.h>
#include <math.h>
#include <stdint.h>

#define NUM_SCALES 16
#define MAXP 524288u
#define HMASK (MAXP - 1u)
#define TPB 128
#define NBINS (1 << 20)
#define MAXQ 1048576
#define NTILE 1024   // scan tiles (each covers 1024 bins)

struct Cfg {
    float rx[NUM_SCALES], ry[NUM_SCALES], rz[NUM_SCALES], rt[NUM_SCALES];
    unsigned s1[NUM_SCALES], s2[NUM_SCALES], s3[NUM_SCALES];
    unsigned dense[NUM_SCALES];
    unsigned off2[NUM_SCALES];   // level offset in float2 units (16B-aligned: p % 8 == 0)
};

// ---- scratch (static device globals; no allocation) ----
// g_cnt: histogram counters. INVARIANT: all-zero at the start of every
// kernel_launch call (zero-initialized at load; scan_p3 re-zeros it each run).
__device__ int g_cnt[NBINS];
__device__ int g_off[NBINS];    // exclusive prefix offsets (read-only after scan_p3)
__device__ int g_bsum[NTILE];
__device__ unsigned g_key[MAXQ];   // [31:20] within-bin rank, [19:0] Morton bin
__device__ int g_perm[MAXQ];

// ---- Morton key: 5 bits per dim interleaved -> 20-bit key ----
__device__ __forceinline__ unsigned spread5(unsigned v) {
    return (v & 1u) | ((v & 2u) << 3) | ((v & 4u) << 6) | ((v & 8u) << 9) | ((v & 16u) << 12);
}
__device__ __forceinline__ unsigned morton_key(float4 p) {
    unsigned kx = (unsigned)(p.x * 32.0f);
    unsigned ky = (unsigned)(p.y * 32.0f);
    unsigned kz = (unsigned)(p.z * 32.0f);
    unsigned kt = (unsigned)(p.w * 32.0f);
    kx = kx > 31u ? 31u : kx; ky = ky > 31u ? 31u : ky;
    kz = kz > 31u ? 31u : kz; kt = kt > 31u ? 31u : kt;
    return spread5(kx) | (spread5(ky) << 1) | (spread5(kz) << 2) | (spread5(kt) << 3);
}

// histogram; the atomic's return value IS the within-bin rank -> pack into key
__global__ void hist_kernel(const float4* __restrict__ xyzt, int nq) {
    int i = blockIdx.x * blockDim.x + threadIdx.x;
    if (i < nq) {
        unsigned k = morton_key(xyzt[i]);
        unsigned r = (unsigned)atomicAdd(&g_cnt[k], 1);
        g_key[i] = k | (r << 20);
    }
}

// phase 1: per-tile sums (1024 tiles x 1024 bins), shuffle reduction
__global__ __launch_bounds__(256) void scan_p1() {
    __shared__ int warpsum[8];
    int t = threadIdx.x;
    int4 v = ((const int4*)g_cnt)[blockIdx.x * 256 + t];
    int s = v.x + v.y + v.z + v.w;
#pragma unroll
    for (int off = 16; off > 0; off >>= 1)
        s += __shfl_down_sync(0xFFFFFFFFu, s, off);
    if ((t & 31) == 0) warpsum[t >> 5] = s;
    __syncthreads();
    if (t < 8) {
        int w = warpsum[t];
#pragma unroll
        for (int off = 4; off > 0; off >>= 1)
            w += __shfl_down_sync(0xFFu, w, off);
        if (t == 0) g_bsum[blockIdx.x] = w;
    }
}

// phase 2+3 fused: every block redundantly scans the 1024 tile sums to get its
// own exclusive base, does its local scan into g_off, and RE-ZEROS g_cnt.
__global__ __launch_bounds__(256) void scan_p3() {
    __shared__ int sc[256];
    __shared__ int tilebase_sh;
    int t = threadIdx.x;

    {
        int4 b4 = ((const int4*)g_bsum)[t];            // tiles 4t..4t+3
        int mysum = b4.x + b4.y + b4.z + b4.w;
        int lane = t & 31, wid = t >> 5;
        int val = mysum;
#pragma unroll
        for (int off = 1; off < 32; off <<= 1) {
            int u = __shfl_up_sync(0xFFFFFFFFu, val, off);
            if (lane >= off) val += u;
        }
        __shared__ int wtot[8];
        if (lane == 31) wtot[wid] = val;
        __syncthreads();
        int wbase = 0;
#pragma unroll
        for (int w = 0; w < 8; ++w) wbase += (w < wid) ? wtot[w] : 0;
        int thr_excl = wbase + val - mysum;
        int tgt = blockIdx.x >> 2, slot = blockIdx.x & 3;
        if (t == tgt) {
            int base = thr_excl;
            if (slot > 0) base += b4.x;
            if (slot > 1) base += b4.y;
            if (slot > 2) base += b4.z;
            tilebase_sh = base;
        }
        __syncthreads();
    }
    int tilebase = tilebase_sh;

    int gi = blockIdx.x * 256 + t;
    int4 v = ((const int4*)g_cnt)[gi];
    int tsum = v.x + v.y + v.z + v.w;
    sc[t] = tsum;
    __syncthreads();
    for (int off = 1; off < 256; off <<= 1) {
        int u = (t >= off) ? sc[t - off] : 0;
        __syncthreads();
        sc[t] += u;
        __syncthreads();
    }
    int base = tilebase + sc[t] - tsum;
    int4 o;
    o.x = base;
    o.y = base + v.x;
    o.z = base + v.x + v.y;
    o.w = base + v.x + v.y + v.z;
    ((int4*)g_off)[gi] = o;
    ((int4*)g_cnt)[gi] = make_int4(0, 0, 0, 0);   // reset for next replay
}

// scatter: atomic-free, batch-8 staged loads for maximum MLP.
// phase 1: 8 key loads in flight; phase 2: 8 g_off gathers in flight;
// phase 3: 8 scattered stores. No per-element dependent chain.
__global__ void scatter_kernel(int nq) {
    int i0 = (blockIdx.x * blockDim.x + threadIdx.x) * 8;
    unsigned kr[8];
    int pos[8];
    bool full = (i0 + 7 < nq);
    if (full) {
#pragma unroll
        for (int u = 0; u < 8; ++u) kr[u] = __ldcs(&g_key[i0 + u]);
#pragma unroll
        for (int u = 0; u < 8; ++u) pos[u] = __ldg(&g_off[kr[u] & 0xFFFFFu]) + (int)(kr[u] >> 20);
#pragma unroll
        for (int u = 0; u < 8; ++u) g_perm[pos[u]] = i0 + u;
    } else {
#pragma unroll
        for (int u = 0; u < 8; ++u) {
            int i = i0 + u;
            if (i < nq) {
                unsigned k = g_key[i];
                g_perm[g_off[k & 0xFFFFFu] + (int)(k >> 20)] = i;
            }
        }
    }
}

// ---------------- main encode ----------------

struct LvlBuf {
    float4 f4[8];     // aligned pair-words: entries {2m, 2m+1} containing corner 2j
    float2 fb[8];     // fallback load of corner 2j+1 when pair not adjacent
    float fx, fy, fz, ft;
    unsigned masks;   // bits 0-7: corner 2j in high half; bits 8-15: pair adjacent
};

__device__ __forceinline__ void level_issue(
    const Cfg& cfg, int s, float4 p, const float2* __restrict__ tbl,
    LvlBuf& B)
{
    float px = p.x * cfg.rx[s];
    float py = p.y * cfg.ry[s];
    float pz = p.z * cfg.rz[s];
    float pt = p.w * cfg.rt[s];
    float gx = floorf(px), gy = floorf(py), gz = floorf(pz), gt = floorf(pt);
    B.fx = px - gx; B.fy = py - gy; B.fz = pz - gz; B.ft = pt - gt;
    unsigned ix = (unsigned)(int)gx, iy = (unsigned)(int)gy;
    unsigned iz = (unsigned)(int)gz, it = (unsigned)(int)gt;

    const float2* __restrict__ base = tbl + cfg.off2[s];
    const float4* __restrict__ base4 = (const float4*)base;

    unsigned a[8], b[8];
    if (cfg.dense[s]) {
        unsigned t1 = cfg.s1[s], t2 = cfg.s2[s], t3 = cfg.s3[s];
        unsigned b0 = ix + iy * t1 + iz * t2 + it * t3;
#pragma unroll
        for (int j = 0; j < 8; ++j) {
            unsigned byzt = b0 + ((j & 1) ? t1 : 0u) + ((j & 2) ? t2 : 0u) + ((j & 4) ? t3 : 0u);
            a[j] = byzt;
            b[j] = byzt + 1u;
        }
    } else {
        unsigned hy0 = iy * 2654435761u, hy1 = (iy + 1u) * 2654435761u;
        unsigned hz0 = iz * 805459861u,  hz1 = (iz + 1u) * 805459861u;
        unsigned ht0 = it * 3674653429u, ht1 = (it + 1u) * 3674653429u;
#pragma unroll
        for (int j = 0; j < 8; ++j) {
            unsigned r = ((j & 1) ? hy1 : hy0) ^ ((j & 2) ? hz1 : hz0) ^ ((j & 4) ? ht1 : ht0);
            a[j] = (ix ^ r) & HMASK;
            b[j] = ((ix + 1u) ^ r) & HMASK;
        }
    }

    unsigned masks = 0u;
#pragma unroll
    for (int j = 0; j < 8; ++j) {
        B.f4[j] = __ldg(base4 + (a[j] >> 1));
        masks |= (a[j] & 1u) << j;
        masks |= ((a[j] ^ b[j]) == 1u ? 256u : 0u) << j;
    }
#pragma unroll
    for (int j = 0; j < 8; ++j) {
        if ((a[j] ^ b[j]) != 1u)
            B.fb[j] = __ldg(base + b[j]);
    }
    B.masks = masks;
}

__device__ __forceinline__ float2 level_consume(const LvlBuf& B)
{
    float fx = B.fx, fy = B.fy, fz = B.fz, ft = B.ft;
    float wx0 = 1.f - fx, wy0 = 1.f - fy, wz0 = 1.f - fz, wt0 = 1.f - ft;
    float wxy[4] = {wx0 * wy0, fx * wy0, wx0 * fy, fx * fy};
    float wzt[4] = {wz0 * wt0, fz * wt0, wz0 * ft, fz * ft};

    float o0 = 0.f, o1 = 0.f;
#pragma unroll
    for (int j = 0; j < 8; ++j) {
        bool hi  = (B.masks >> j) & 1u;
        bool adj = (B.masks >> (j + 8)) & 1u;
        float4 q = B.f4[j];
        float c0x = hi ? q.z : q.x, c0y = hi ? q.w : q.y;
        float c1x = hi ? q.x : q.z, c1y = hi ? q.y : q.w;
        if (!adj) { c1x = B.fb[j].x; c1y = B.fb[j].y; }
        float wz = wzt[j >> 1];
        float w0 = wxy[(j & 1) * 2]     * wz;
        float w1 = wxy[(j & 1) * 2 + 1] * wz;
        o0 = fmaf(w0, c0x, o0); o1 = fmaf(w0, c0y, o1);
        o0 = fmaf(w1, c1x, o0); o1 = fmaf(w1, c1y, o1);
    }
    return make_float2(o0, o1);
}

__global__ __launch_bounds__(TPB, 3) void henc_kernel(
    const float4* __restrict__ xyzt,
    const float2* __restrict__ tbl,
    float2* __restrict__ out2,
    Cfg cfg, int nq)
{
    __shared__ float2 sm2[TPB * 17];
    __shared__ int qsh[TPB];
    const int tid = threadIdx.x;
    const int i = blockIdx.x * TPB + tid;

    int q = (i < nq) ? __ldcs(&g_perm[i]) : -1;   // read-once stream
    qsh[tid] = q;
    float4 p = (q >= 0) ? __ldg(&xyzt[q]) : make_float4(0.f, 0.f, 0.f, 0.f);

    LvlBuf A, B;
    level_issue(cfg, 0, p, tbl, A);

#pragma unroll 1
    for (int s = 0; s < NUM_SCALES; s += 2) {
        level_issue(cfg, s + 1, p, tbl, B);
        sm2[tid * 17 + s] = level_consume(A);
        if (s + 2 < NUM_SCALES)
            level_issue(cfg, s + 2, p, tbl, A);
        sm2[tid * 17 + s + 1] = level_consume(B);
    }

    __syncthreads();

    // scattered row store, streaming policy: write-once output must not evict
    // the hash table from L2 (61MB table vs 128MB output stream)
#pragma unroll
    for (int k = 0; k < 16; ++k) {
        int m = tid + k * TPB;
        int row = m >> 4, chunk = m & 15;
        int qr = qsh[row];
        if (qr >= 0) __stcs(&out2[qr * 16 + chunk], sm2[row * 17 + chunk]);
    }
}

extern "C" void kernel_launch(void* const* d_in, const int* in_sizes, int n_in,
                              void* d_out, int out_size)
{
    (void)n_in; (void)out_size;

    // Rebuild the reference's build_config() with the same float64 libm math.
    Cfg cfg;
    const double minr[4] = {16.0, 16.0, 16.0, 16.0};
    const double maxr[4] = {256.0, 256.0, 256.0, 128.0};
    double b[4];
    for (int d = 0; d < 4; ++d)
        b[d] = exp((log(maxr[d]) - log(minr[d])) / (double)(NUM_SCALES - 1));

    unsigned long long totalp = 0;
    for (int s = 0; s < NUM_SCALES; ++s) {
        long long res[4];
        for (int d = 0; d < 4; ++d)
            res[d] = (long long)ceil(minr[d] * pow(b[d], (double)s));
        long long raw = (res[0] + 1) * (res[1] + 1) * (res[2] + 1) * (res[3] + 1);
        long long pp = (raw % 8 == 0) ? raw : ((raw + 7) / 8) * 8;
        if (pp > (long long)MAXP) pp = (long long)MAXP;

        cfg.dense[s] = (raw <= pp) ? 1u : 0u;
        cfg.rx[s] = (float)res[0];
        cfg.ry[s] = (float)res[1];
        cfg.rz[s] = (float)res[2];
        cfg.rt[s] = (float)res[3];
        cfg.s1[s] = (unsigned)(res[0] + 1);
        cfg.s2[s] = (unsigned)((res[0] + 1) * (res[1] + 1));
        cfg.s3[s] = (unsigned)((res[0] + 1) * (res[1] + 1) * (res[2] + 1));
        cfg.off2[s] = (unsigned)totalp;
        totalp += (unsigned long long)pp;
    }

    int nq = in_sizes[0] / 4;
    const float4* xyzt = (const float4*)d_in[0];
    const float2* tbl  = (const float2*)d_in[1];
    float2* out2 = (float2*)d_out;

    // 1) Morton binning (counting sort, 2^20 bins). g_cnt is all-zero here:
    //    zero-init at module load, re-zeroed by scan_p3 on every run.
    hist_kernel<<<(nq + 255) / 256, 256>>>(xyzt, nq);
    scan_p1<<<NTILE, 256>>>();
    scan_p3<<<NTILE, 256>>>();   // tile-base scan + local scan -> g_off; zeros g_cnt
    scatter_kernel<<<(nq + 2047) / 2048, 256>>>(nq);

    // 2) encode in sorted order
    int blocks = (nq + TPB - 1) / TPB;
    henc_kernel<<<blocks, TPB>>>(xyzt, tbl, out2, cfg, nq);
}